// round 1
// baseline (speedup 1.0000x reference)
#include <cuda_runtime.h>
#include <math.h>

// ---------------- scratch (static __device__ -- no allocation) ----------------
__device__ float g_p1[4 * 256 * 256];   // pooled conv1 output (n=0)
__device__ float g_p2[16 * 128 * 128];  // pooled conv2 output (n=0)
__device__ float g_vlad[1024];          // vlad accumulator [64,16]
__device__ float g_asum[64];            // soft-assign sums
__device__ float g_feat[512];           // fc output (feat0)
__device__ float g_h[2][512];           // RNN hidden double buffer
__device__ int   g_bar[64];             // per-step spin barrier counters

// ---------------- K0: zero scratch ----------------
__global__ void k_zero(float* dout) {
    int i = blockIdx.x * blockDim.x + threadIdx.x;
    if (i < 1024) g_vlad[i] = 0.f;
    if (i < 64)  g_asum[i] = 0.f;
    if (i < 64)  g_bar[i]  = 0;
    if (i == 0)  dout[0]   = 0.f;
}

// ---------------- K1: conv1(3->4) + relu + avgpool2, n=0 ----------------
// img0 [3,512,512] -> g_p1 [4,256,256]
__global__ void k_conv1(const float* __restrict__ img,
                        const float* __restrict__ w,
                        const float* __restrict__ b) {
    __shared__ float t[3][34][34];
    __shared__ float ws[108];
    __shared__ float bs[4];
    int tx = threadIdx.x, ty = threadIdx.y;
    int tid = ty * 16 + tx;
    if (tid < 108) ws[tid] = w[tid];
    if (tid < 4)   bs[tid] = b[tid];
    int gy0 = blockIdx.y * 32 - 1;
    int gx0 = blockIdx.x * 32 - 1;
    for (int i = tid; i < 3 * 34 * 34; i += 256) {
        int c = i / (34 * 34);
        int r = (i / 34) % 34;
        int q = i % 34;
        int gy = gy0 + r, gx = gx0 + q;
        float v = 0.f;
        if (gy >= 0 && gy < 512 && gx >= 0 && gx < 512)
            v = img[c * 512 * 512 + gy * 512 + gx];
        t[c][r][q] = v;
    }
    __syncthreads();
    int ly = 2 * ty, lx = 2 * tx;
    float win[3][4][4];
#pragma unroll
    for (int c = 0; c < 3; c++)
#pragma unroll
        for (int r = 0; r < 4; r++)
#pragma unroll
            for (int q = 0; q < 4; q++)
                win[c][r][q] = t[c][ly + r][lx + q];
    float acc[4] = {0.f, 0.f, 0.f, 0.f};
#pragma unroll
    for (int dy = 0; dy < 2; dy++)
#pragma unroll
        for (int dx = 0; dx < 2; dx++) {
#pragma unroll
            for (int oc = 0; oc < 4; oc++) {
                float s = bs[oc];
#pragma unroll
                for (int c = 0; c < 3; c++)
#pragma unroll
                    for (int ky = 0; ky < 3; ky++)
#pragma unroll
                        for (int kx = 0; kx < 3; kx++)
                            s += win[c][dy + ky][dx + kx] * ws[oc * 27 + c * 9 + ky * 3 + kx];
                acc[oc] += fmaxf(s, 0.f);
            }
        }
    int py = blockIdx.y * 16 + ty, px = blockIdx.x * 16 + tx;
#pragma unroll
    for (int oc = 0; oc < 4; oc++)
        g_p1[oc * 65536 + py * 256 + px] = acc[oc] * 0.25f;
}

// ---------------- K2: conv2(4->16) + relu + avgpool2 ----------------
// g_p1 [4,256,256] -> g_p2 [16,128,128]; blockIdx.z selects 8 output channels
__global__ void k_conv2(const float* __restrict__ w,
                        const float* __restrict__ b) {
    __shared__ float t[4][34][34];
    __shared__ float ws[288];
    __shared__ float bs[8];
    int tx = threadIdx.x, ty = threadIdx.y;
    int tid = ty * 16 + tx;
    int oc0 = blockIdx.z * 8;
    if (tid < 288) ws[tid] = w[oc0 * 36 + tid];
    if (tid < 8)   bs[tid] = b[oc0 + tid];
    int gy0 = blockIdx.y * 32 - 1;
    int gx0 = blockIdx.x * 32 - 1;
    for (int i = tid; i < 4 * 34 * 34; i += 256) {
        int c = i / (34 * 34);
        int r = (i / 34) % 34;
        int q = i % 34;
        int gy = gy0 + r, gx = gx0 + q;
        float v = 0.f;
        if (gy >= 0 && gy < 256 && gx >= 0 && gx < 256)
            v = g_p1[c * 65536 + gy * 256 + gx];
        t[c][r][q] = v;
    }
    __syncthreads();
    int ly = 2 * ty, lx = 2 * tx;
    float win[4][4][4];
#pragma unroll
    for (int c = 0; c < 4; c++)
#pragma unroll
        for (int r = 0; r < 4; r++)
#pragma unroll
            for (int q = 0; q < 4; q++)
                win[c][r][q] = t[c][ly + r][lx + q];
    float acc[8];
#pragma unroll
    for (int oc = 0; oc < 8; oc++) acc[oc] = 0.f;
#pragma unroll
    for (int dy = 0; dy < 2; dy++)
#pragma unroll
        for (int dx = 0; dx < 2; dx++) {
#pragma unroll
            for (int oc = 0; oc < 8; oc++) {
                float s = bs[oc];
#pragma unroll
                for (int c = 0; c < 4; c++)
#pragma unroll
                    for (int ky = 0; ky < 3; ky++)
#pragma unroll
                        for (int kx = 0; kx < 3; kx++)
                            s += win[c][dy + ky][dx + kx] * ws[oc * 36 + c * 9 + ky * 3 + kx];
                acc[oc] += fmaxf(s, 0.f);
            }
        }
    int py = blockIdx.y * 16 + ty, px = blockIdx.x * 16 + tx;
#pragma unroll
    for (int oc = 0; oc < 8; oc++)
        g_p2[(oc0 + oc) * 16384 + py * 128 + px] = acc[oc] * 0.25f;
}

// ---------------- K3: NetVLAD soft-assign + accumulate ----------------
// 128 blocks x 128 threads; each block handles 128 hw positions
__global__ void k_nvlad(const float* __restrict__ nvw,
                        const float* __restrict__ nvb) {
    extern __shared__ float sm[];
    float* xt = sm;                 // [16][128]
    float* at = sm + 16 * 128;      // [64][136] (padded)
    float* ws = at + 64 * 136;      // [64*16]
    float* bs = ws + 1024;          // [64]
    int tid = threadIdx.x;
    int h0 = blockIdx.x * 128;
    for (int i = tid; i < 1024; i += 128) ws[i] = nvw[i];
    if (tid < 64) bs[tid] = nvb[tid];
    float xv[16];
#pragma unroll
    for (int c = 0; c < 16; c++) {
        float v = g_p2[c * 16384 + h0 + tid];
        xt[c * 128 + tid] = v;
        xv[c] = v;
    }
    __syncthreads();
    float a[64];
    float mx = -1e30f;
#pragma unroll
    for (int k = 0; k < 64; k++) {
        float s = bs[k];
#pragma unroll
        for (int c = 0; c < 16; c++) s += ws[k * 16 + c] * xv[c];
        a[k] = s;
        mx = fmaxf(mx, s);
    }
    float den = 0.f;
#pragma unroll
    for (int k = 0; k < 64; k++) {
        float e = __expf(a[k] - mx);
        a[k] = e;
        den += e;
    }
    float inv = 1.f / den;
#pragma unroll
    for (int k = 0; k < 64; k++) at[k * 136 + tid] = a[k] * inv;
    __syncthreads();
#pragma unroll
    for (int j = 0; j < 8; j++) {
        int idx = tid + 128 * j;
        int k = idx >> 4, c = idx & 15;
        float acc = 0.f;
        for (int h = 0; h < 128; h++) acc += at[k * 136 + h] * xt[c * 128 + h];
        atomicAdd(&g_vlad[idx], acc);
    }
    if (tid < 64) {
        float s = 0.f;
        for (int h = 0; h < 128; h++) s += at[tid * 136 + h];
        atomicAdd(&g_asum[tid], s);
    }
}

// ---------------- K4: finalize vlad + norms + fc ----------------
__global__ void k_final(const float* __restrict__ cent,
                        const float* __restrict__ fcw,
                        const float* __restrict__ fcb) {
    __shared__ float v[1024];
    __shared__ float invk[64];
    __shared__ float red[16];
    __shared__ float totS;
    int tid = threadIdx.x;  // 512 threads
    for (int i = tid; i < 1024; i += 512)
        v[i] = g_vlad[i] - g_asum[i >> 4] * cent[i];
    __syncthreads();
    if (tid < 64) {
        float s = 0.f;
#pragma unroll
        for (int c = 0; c < 16; c++) {
            float x = v[tid * 16 + c];
            s += x * x;
        }
        invk[tid] = 1.f / fmaxf(sqrtf(s), 1e-12f);
    }
    __syncthreads();
    float ss = 0.f;
    for (int i = tid; i < 1024; i += 512) {
        float x = v[i] * invk[i >> 4];
        v[i] = x;
        ss += x * x;
    }
#pragma unroll
    for (int o = 16; o > 0; o >>= 1) ss += __shfl_xor_sync(0xffffffffu, ss, o);
    if ((tid & 31) == 0) red[tid >> 5] = ss;
    __syncthreads();
    if (tid == 0) {
        float t = 0.f;
        for (int i = 0; i < 16; i++) t += red[i];
        totS = 1.f / fmaxf(sqrtf(t), 1e-12f);
    }
    __syncthreads();
    float inv2 = totS;
    for (int i = tid; i < 1024; i += 512) v[i] *= inv2;
    __syncthreads();
    int wid = tid >> 5, lane = tid & 31;
    for (int j = 0; j < 32; j++) {
        int row = wid * 32 + j;
        float s = 0.f;
        for (int i = lane; i < 1024; i += 32) s += fcw[row * 1024 + i] * v[i];
#pragma unroll
        for (int o = 16; o > 0; o >>= 1) s += __shfl_xor_sync(0xffffffffu, s, o);
        if (lane == 0) {
            float f = s + fcb[row];
            g_feat[row] = f;
            g_h[0][row] = f;
        }
    }
}

// ---------------- K5: sequential RNN + loss ----------------
// 64 CTAs x 256 threads, persistent, global spin barrier per step.
// CTA b: hidden rows [8b, 8b+8); output rows [5b, 5b+5) for b<60.
__global__ void k_rnn(const float* __restrict__ cap,
                      const float* __restrict__ hw,
                      const float* __restrict__ hb,
                      const float* __restrict__ ow,
                      const float* __restrict__ ob,
                      float* dout) {
    __shared__ float Wh[8][812];
    __shared__ float Wo[5][512];
    __shared__ float comb[812];
    __shared__ float hbs[8], obs[5];
    __shared__ float lossS;
    int b = blockIdx.x, tid = threadIdx.x;
    int hr0 = b * 8;
    for (int i = tid; i < 8 * 812; i += 256) {
        int r = i / 812, c = i % 812;
        Wh[r][c] = hw[(hr0 + r) * 812 + c];
    }
    if (tid < 8) hbs[tid] = hb[hr0 + tid];
    bool hasOut = (b < 60);
    int or0 = b * 5;
    if (hasOut) {
        for (int i = tid; i < 5 * 512; i += 256) {
            int r = i / 512, c = i % 512;
            Wo[r][c] = ow[(or0 + r) * 512 + c];
        }
        if (tid < 5) obs[tid] = ob[or0 + tid];
    }
    if (tid == 0) lossS = 0.f;
    // initial comb: x = cap0[0], h = feat0
    for (int i = tid; i < 300; i += 256) comb[i] = cap[i];
    for (int i = tid; i < 512; i += 256) comb[300 + i] = g_h[0][i];
    __syncthreads();
    int wid = tid >> 5, lane = tid & 31;
    float lacc = 0.f;
    for (int t = 0; t < 63; t++) {
        // hidden matvec: warp wid -> hidden row hr0+wid
        float s = 0.f;
        const float* wr = Wh[wid];
        for (int c = lane; c < 812; c += 32) s += wr[c] * comb[c];
#pragma unroll
        for (int o = 16; o > 0; o >>= 1) s += __shfl_xor_sync(0xffffffffu, s, o);
        if (lane == 0) {
            float hn = 1.f / (1.f + __expf(-(s + hbs[wid])));
            g_h[(t + 1) & 1][hr0 + wid] = hn;
            __threadfence();
        }
        __syncthreads();
        if (tid == 0) {
            atomicAdd(&g_bar[t], 1);
            while (((volatile int*)g_bar)[t] < 64) { }
            __threadfence();
        }
        __syncthreads();
        // refresh comb: x = cap0[t+1], h = h_{t+1} (L2-coherent loads)
        for (int i = tid; i < 300; i += 256) comb[i] = cap[(t + 1) * 300 + i];
        {
            const float* hp = g_h[(t + 1) & 1];
            for (int i = tid; i < 512; i += 256) comb[300 + i] = __ldcg(hp + i);
        }
        __syncthreads();
        // output matvec + loss: y_t vs cap0[t+1]
        if (hasOut && wid < 5) {
            float s2 = 0.f;
            const float* wo = Wo[wid];
            const float* hc = comb + 300;
            for (int c = lane; c < 512; c += 32) s2 += wo[c] * hc[c];
#pragma unroll
            for (int o = 16; o > 0; o >>= 1) s2 += __shfl_xor_sync(0xffffffffu, s2, o);
            if (lane == 0) {
                float y = 1.f / (1.f + __expf(-(s2 + obs[wid])));
                float d = y - comb[or0 + wid];
                lacc += d * d;
            }
        }
    }
    if (hasOut && wid < 5 && lane == 0) atomicAdd(&lossS, lacc);
    __syncthreads();
    if (tid == 0 && hasOut) atomicAdd(dout, lossS * (1.f / 19200.f));
}

// ---------------- launcher ----------------
extern "C" void kernel_launch(void* const* d_in, const int* in_sizes, int n_in,
                              void* d_out, int out_size) {
    const float* img     = (const float*)d_in[0];
    const float* cap     = (const float*)d_in[1];
    const float* conv1_w = (const float*)d_in[2];
    const float* conv1_b = (const float*)d_in[3];
    const float* conv2_w = (const float*)d_in[4];
    const float* conv2_b = (const float*)d_in[5];
    const float* cent    = (const float*)d_in[6];
    const float* nv_w    = (const float*)d_in[7];
    const float* nv_b    = (const float*)d_in[8];
    const float* fc_w    = (const float*)d_in[9];
    const float* fc_b    = (const float*)d_in[10];
    const float* hid_w   = (const float*)d_in[11];
    const float* hid_b   = (const float*)d_in[12];
    const float* out_w   = (const float*)d_in[13];
    const float* out_b   = (const float*)d_in[14];
    float* dout = (float*)d_out;

    static bool attr_set = false;
    if (!attr_set) {
        cudaFuncSetAttribute(k_nvlad, cudaFuncAttributeMaxDynamicSharedMemorySize, 64 * 1024);
        attr_set = true;
    }

    k_zero<<<4, 256>>>(dout);
    k_conv1<<<dim3(16, 16), dim3(16, 16)>>>(img, conv1_w, conv1_b);
    k_conv2<<<dim3(8, 8, 2), dim3(16, 16)>>>(conv2_w, conv2_b);
    size_t smem3 = (size_t)(16 * 128 + 64 * 136 + 1024 + 64) * sizeof(float);
    k_nvlad<<<128, 128, smem3>>>(nv_w, nv_b);
    k_final<<<1, 512>>>(cent, fc_w, fc_b);
    k_rnn<<<64, 256>>>(cap, hid_w, hid_b, out_w, out_b, dout);
}